// round 10
// baseline (speedup 1.0000x reference)
#include <cuda_runtime.h>

#define TPB     256
#define NBLOCKS 1216
#define SB      2048      // superblock: 8 chunks of TPB elements
#define LMIN    1024      // rows shorter than this go to the corner path

// ---------------------------------------------------------------------------
// out = sum_i x[i]*c[i] + sum_{i<j} x[i]*x[j]*c2[base(i)+(j-i-1)]
// c2 = c + n, base(i) = i*(2n-1-i)/2  (row-major packed upper triangle).
//
// Main region = rows 0..n-LMIN-1 (every row length >= LMIN): flat-partitioned
// into 2048-element superblocks; each block streams a CONTIGUOUS run of
// superblocks front-to-back (1216 purely sequential DRAM streams). Inside a
// superblock at most 2 row boundaries exist, so x[i]/j-offset are a 3-way
// SELECT on g; the 8 coeff loads depend only on the induction variable.
// Corner region (last LMIN rows, 1.6% of elems) + leftovers: per-element
// sqrt decode, grid-strided.
// ---------------------------------------------------------------------------

__global__ void zero_out_kernel(float* out) {
    if (threadIdx.x == 0 && blockIdx.x == 0) out[0] = 0.0f;
}

__device__ __forceinline__ float warp_sum(float v) {
    #pragma unroll
    for (int o = 16; o > 0; o >>= 1) v += __shfl_down_sync(0xffffffffu, v, o);
    return v;
}

__global__ __launch_bounds__(TPB)
void ham_kernel(const float* __restrict__ x,
                const float* __restrict__ c,
                float* __restrict__ out,
                int n) {
    const int t = threadIdx.x;
    const int b = blockIdx.x;
    const int G = gridDim.x;
    const float* c2 = c + n;

    const int total = (n * (n - 1)) >> 1;                 // 33,550,336
    const int ilong = n - LMIN;                           // 7168
    const int gc    = (ilong * (2 * n - 1 - ilong)) >> 1; // 33,026,560
    const int S     = gc / SB;                            // full superblocks

    float sum = 0.0f;

    // degree-1 terms, spread over all blocks
    for (int k = b * TPB + t; k < n; k += G * TPB)
        sum += __ldg(x + k) * __ldg(c + k);

    // ---- main region: contiguous superblock range per block ----
    const int s0 = (int)(((long long)b       * S) / G);
    const int s1 = (int)(((long long)(b + 1) * S) / G);

    if (s0 < s1) {
        const int g0   = s0 * SB;
        const int gend = s1 * SB;

        // decode starting row (double seed + exact fixup)
        const double nd = 2.0 * (double)n - 1.0;
        int i = (int)((nd - sqrt(nd * nd - 8.0 * (double)g0)) * 0.5);
        if (i < 0) i = 0;
        if (i > n - 2) i = n - 2;
        int rb = (i * (2 * n - 1 - i)) >> 1;
        while (rb > g0) { --i; rb -= (n - 1 - i); }
        while (g0 >= rb + (n - 1 - i)) { rb += (n - 1 - i); ++i; }
        int re = rb + (n - 1 - i);

        for (int gb = g0; gb < gend; gb += SB) {
            // rows A=i, B=i+1, C=i+2 can appear in this superblock
            const int b1 = re;                  // first boundary
            const int b2 = re + (n - 2 - i);    // second boundary
            const float xiA = __ldg(x + i);
            const float xiB = __ldg(x + i + 1);
            const float xiC = __ldg(x + i + 2);
            const int joffA = i + 1 - rb;
            const int joffB = i + 2 - b1;
            const int joffC = i + 3 - b2;

            #pragma unroll
            for (int k = 0; k < SB / TPB; ++k) {
                const int g = gb + k * TPB + t;
                const float cv = __ldcs(c2 + g);     // induction-only address
                float xi;
                int joff;
                if (g >= b2)      { xi = xiC; joff = joffC; }
                else if (g >= b1) { xi = xiB; joff = joffB; }
                else              { xi = xiA; joff = joffA; }
                sum = fmaf(cv, xi * __ldg(x + g + joff), sum);
            }

            // advance row state past this superblock (<= 2 iterations)
            const int gn = gb + SB;
            while (gn >= re && i < n - 2) { rb = re; ++i; re += (n - 1 - i); }
        }
    }

    // ---- tail: [S*SB, total) — leftover main elems + corner rows ----
    const double nd = 2.0 * (double)n - 1.0;
    for (int g = S * SB + b * TPB + t; g < total; g += G * TPB) {
        int i = (int)((nd - sqrt(nd * nd - 8.0 * (double)g)) * 0.5);
        if (i < 0) i = 0;
        if (i > n - 2) i = n - 2;
        int rb = (i * (2 * n - 1 - i)) >> 1;
        while (rb > g) { --i; rb -= (n - 1 - i); }
        while (g >= rb + (n - 1 - i)) { rb += (n - 1 - i); ++i; }
        const int j = g - rb + i + 1;
        sum = fmaf(__ldcs(c2 + g), __ldg(x + i) * __ldg(x + j), sum);
    }

    // block reduction: warp shuffle -> smem -> warp 0 -> one atomic per block
    __shared__ float wsum[TPB / 32];
    float w = warp_sum(sum);
    if ((t & 31) == 0) wsum[t >> 5] = w;
    __syncthreads();
    if (t < 32) {
        float v = (t < TPB / 32) ? wsum[t] : 0.0f;
        v = warp_sum(v);
        if (t == 0) atomicAdd(out, v);
    }
}

extern "C" void kernel_launch(void* const* d_in, const int* in_sizes, int n_in,
                              void* d_out, int out_size) {
    const float* x = (const float*)d_in[0];
    const float* c = (const float*)d_in[1];
    float* out = (float*)d_out;
    const int n = in_sizes[0];   // 8192

    zero_out_kernel<<<1, 32>>>(out);
    ham_kernel<<<NBLOCKS, TPB>>>(x, c, out, n);
}

// round 11
// speedup vs baseline: 1.8172x; 1.8172x over previous
#include <cuda_runtime.h>

#define TPB     256
#define NBLOCKS 608      // ~152 SMs * 4 resident blocks (regs ~60)
#define W       1024     // column-strip width (= 4 * TPB)

// ---------------------------------------------------------------------------
// out = sum_j x[j] * ( c1[j] + sum_{i<j} x[i] * c2[base(i) + (j-i-1)] )
// c2 = c + n, base(i) = i*(2n-1-i)/2  (row-major packed upper triangle).
//
// Thread t owns 4 consecutive columns j_a..j_a+3 (j_a = j0 + 4t) with a
// float4 accumulator. Per row the coeff window is read as TWO aligned
// LDG.128 (f,g) + a row-uniform shift select -> 512B per load instruction,
// 8 loads in flight in the 4-row unrolled body (4KB/warp). Load addresses
// come from integer recurrences only (fully hoistable). Work split =
// element-balanced row-segments (R6 framework).
// ---------------------------------------------------------------------------

__global__ void zero_out_kernel(float* out) {
    if (threadIdx.x == 0 && blockIdx.x == 0) out[0] = 0.0f;
}

__device__ __forceinline__ float warp_sum(float v) {
    #pragma unroll
    for (int o = 16; o > 0; o >>= 1) v += __shfl_down_sync(0xffffffffu, v, o);
    return v;
}

// window = 4 floats starting s (0..3) into the 8-float concat (f, g)
__device__ __forceinline__ float4 win(float4 f, float4 g, int s) {
    float4 w;
    w.x = (s == 0) ? f.x : (s == 1) ? f.y : (s == 2) ? f.z : f.w;
    w.y = (s == 0) ? f.y : (s == 1) ? f.z : (s == 2) ? f.w : g.x;
    w.z = (s == 0) ? f.z : (s == 1) ? f.w : (s == 2) ? g.x : g.y;
    w.w = (s == 0) ? f.w : (s == 1) ? g.x : (s == 2) ? g.y : g.z;
    return w;
}

__global__ __launch_bounds__(TPB, 4)
void ham_kernel(const float* __restrict__ x,
                const float* __restrict__ c,
                float* __restrict__ out,
                int n) {
    const int t = threadIdx.x;
    const int b = blockIdx.x;
    const int G = gridDim.x;
    const float* c2 = c + n;

    const int ns = n / W;                         // 8 strips
    const int U  = W * (ns * (ns + 1) / 2) - ns;  // 36856 row-segments

    const int u0 = (int)(((long long)b       * U) / G);
    const int u1 = (int)(((long long)(b + 1) * U) / G);

    float sum = 0.0f;

    // degree-1 terms, spread over all blocks
    for (int k = b * TPB + t; k < n; k += G * TPB)
        sum += __ldg(x + k) * __ldg(c + k);

    // locate starting strip for unit u0
    int js = 0, P = 0;
    while (P + ((js + 1) * W - 1) <= u0) { P += (js + 1) * W - 1; ++js; }
    int i = u0 - P;
    int u = u0;

    while (u < u1) {
        const int K   = (js + 1) * W - 1;         // rows in this strip
        const int j0  = js * W;
        const int j_a = j0 + 4 * t;

        int iend = i + (u1 - u);
        if (iend > K) iend = K;
        const int iclean = (iend < j0) ? iend : j0;

        float4 acc = make_float4(0.f, 0.f, 0.f, 0.f);
        // pb = start of this strip's coeff window in row i (flat index)
        int pb = ((i * (2 * n - 1 - i)) >> 1) + j0 - i - 1;

        // ---- clean rows, unroll 4: 8 LDG.128 in flight ----
        for (; i + 4 <= iclean; i += 4) {
            const int d   = n - 2 - i;
            const int pb0 = pb;
            const int pb1 = pb0 + d;
            const int pb2 = pb1 + d - 1;
            const int pb3 = pb2 + d - 2;
            const float4* v0 = (const float4*)(c2 + (pb0 & ~3)) + t;
            const float4* v1 = (const float4*)(c2 + (pb1 & ~3)) + t;
            const float4* v2 = (const float4*)(c2 + (pb2 & ~3)) + t;
            const float4* v3 = (const float4*)(c2 + (pb3 & ~3)) + t;
            const float4 f0 = __ldcs(v0); const float4 g0 = __ldcs(v0 + 1);
            const float4 f1 = __ldcs(v1); const float4 g1 = __ldcs(v1 + 1);
            const float4 f2 = __ldcs(v2); const float4 g2 = __ldcs(v2 + 1);
            const float4 f3 = __ldcs(v3); const float4 g3 = __ldcs(v3 + 1);
            const float xi0 = __ldg(x + i);
            const float xi1 = __ldg(x + i + 1);
            const float xi2 = __ldg(x + i + 2);
            const float xi3 = __ldg(x + i + 3);
            const float4 w0 = win(f0, g0, pb0 & 3);
            const float4 w1 = win(f1, g1, pb1 & 3);
            const float4 w2 = win(f2, g2, pb2 & 3);
            const float4 w3 = win(f3, g3, pb3 & 3);
            acc.x = fmaf(xi0, w0.x, acc.x);  acc.y = fmaf(xi0, w0.y, acc.y);
            acc.z = fmaf(xi0, w0.z, acc.z);  acc.w = fmaf(xi0, w0.w, acc.w);
            acc.x = fmaf(xi1, w1.x, acc.x);  acc.y = fmaf(xi1, w1.y, acc.y);
            acc.z = fmaf(xi1, w1.z, acc.z);  acc.w = fmaf(xi1, w1.w, acc.w);
            acc.x = fmaf(xi2, w2.x, acc.x);  acc.y = fmaf(xi2, w2.y, acc.y);
            acc.z = fmaf(xi2, w2.z, acc.z);  acc.w = fmaf(xi2, w2.w, acc.w);
            acc.x = fmaf(xi3, w3.x, acc.x);  acc.y = fmaf(xi3, w3.y, acc.y);
            acc.z = fmaf(xi3, w3.z, acc.z);  acc.w = fmaf(xi3, w3.w, acc.w);
            pb = pb3 + d - 3;
        }
        // clean remainder (< 4 rows)
        for (; i < iclean; ++i) {
            const float4* v = (const float4*)(c2 + (pb & ~3)) + t;
            const float4 f = __ldcs(v);
            const float4 g = __ldcs(v + 1);
            const float4 w = win(f, g, pb & 3);
            const float xi = __ldg(x + i);
            acc.x = fmaf(xi, w.x, acc.x);  acc.y = fmaf(xi, w.y, acc.y);
            acc.z = fmaf(xi, w.z, acc.z);  acc.w = fmaf(xi, w.w, acc.w);
            pb += n - 2 - i;
        }
        // ---- partial rows (cross the diagonal inside this strip) ----
        for (; i < iend; ++i) {
            if (j_a + 3 > i) {   // lanes entirely below diagonal skip loads
                const float4* v = (const float4*)(c2 + (pb & ~3)) + t;
                const float4 f = __ldcs(v);
                const float4 g = __ldcs(v + 1);
                const float4 w = win(f, g, pb & 3);
                const float xi = __ldg(x + i);
                if (j_a     > i) acc.x = fmaf(xi, w.x, acc.x);
                if (j_a + 1 > i) acc.y = fmaf(xi, w.y, acc.y);
                if (j_a + 2 > i) acc.z = fmaf(xi, w.z, acc.z);
                /* j_a+3 > i */  acc.w = fmaf(xi, w.w, acc.w);
            }
            pb += n - 2 - i;
        }

        // fold by x[j] once per strip (aligned float4)
        const float4 xj = __ldg((const float4*)(x + j_a));
        sum += acc.x * xj.x + acc.y * xj.y + acc.z * xj.z + acc.w * xj.w;

        u = P + i;
        if (i == K) { P += K; ++js; i = 0; }
    }

    // block reduction: warp shuffle -> smem -> warp 0 -> one atomic per block
    __shared__ float wsum[TPB / 32];
    float w = warp_sum(sum);
    if ((t & 31) == 0) wsum[t >> 5] = w;
    __syncthreads();
    if (t < 32) {
        float v = (t < TPB / 32) ? wsum[t] : 0.0f;
        v = warp_sum(v);
        if (t == 0) atomicAdd(out, v);
    }
}

extern "C" void kernel_launch(void* const* d_in, const int* in_sizes, int n_in,
                              void* d_out, int out_size) {
    const float* x = (const float*)d_in[0];
    const float* c = (const float*)d_in[1];
    float* out = (float*)d_out;
    const int n = in_sizes[0];   // 8192

    zero_out_kernel<<<1, 32>>>(out);
    ham_kernel<<<NBLOCKS, TPB>>>(x, c, out, n);
}

// round 12
// speedup vs baseline: 1.9737x; 1.0861x over previous
#include <cuda_runtime.h>

#define TPB   256
#define NBLK  912       // 152 SMs * 6 resident blocks
#define LMIN  1040      // min row length in the chunked main region

// ---------------------------------------------------------------------------
// out = sum_i x[i]*c[i] + sum_{i<j} x[i]*x[j]*c2[base(i)+(j-i-1)]
// c2 = c + n, base(i) = i*(2n-1-i)/2  (row-major packed upper triangle).
//
// Main region (rows 0 .. n-LMIN-1, every row >= LMIN long): flat array split
// into 1024-float chunks; each block streams a CONTIGUOUS chunk range
// (sequential DRAM stream, aligned LDG.128, induction-only addresses).
// Per chunk, thread t covers elements cb+4t..+3: j = g + joff (joff uniform
// per row) -> x window = 2 aligned float4 L1 reads + uniform shift select.
// A chunk holds at most ONE row boundary (rows > 1024): boundary chunks use
// a scalar-select path. Corner region is per-element with sqrt decode.
// Single kernel: block partials + wrap-around arrival counter; last block
// reduces partials deterministically and writes out[0].
// ---------------------------------------------------------------------------

__device__ float        g_parts[NBLK];
__device__ unsigned int g_ctr = 0;

__device__ __forceinline__ float warp_sum(float v) {
    #pragma unroll
    for (int o = 16; o > 0; o >>= 1) v += __shfl_down_sync(0xffffffffu, v, o);
    return v;
}

// 4-float window starting s (0..3) into the 8-float concat (f, g)
__device__ __forceinline__ float4 win(float4 f, float4 g, int s) {
    float4 w;
    w.x = (s == 0) ? f.x : (s == 1) ? f.y : (s == 2) ? f.z : f.w;
    w.y = (s == 0) ? f.y : (s == 1) ? f.z : (s == 2) ? f.w : g.x;
    w.z = (s == 0) ? f.z : (s == 1) ? f.w : (s == 2) ? g.x : g.y;
    w.w = (s == 0) ? f.w : (s == 1) ? g.x : (s == 2) ? g.y : g.z;
    return w;
}

__global__ __launch_bounds__(TPB, 6)
void ham_kernel(const float* __restrict__ x,
                const float* __restrict__ c,
                float* __restrict__ out,
                int n) {
    const int t = threadIdx.x;
    const int b = blockIdx.x;
    const int G = gridDim.x;
    const float* c2 = c + n;

    const int total = (n * (n - 1)) >> 1;                 // 33,550,336
    const int ilong = n - LMIN;                           // 7152
    const int gc    = (ilong * (2 * n - 1 - ilong)) >> 1; // 33,010,056
    const int CHM   = gc >> 10;                           // 32,236 chunks

    float sum = 0.0f;

    // degree-1 terms
    for (int k = b * TPB + t; k < n; k += G * TPB)
        sum += __ldg(x + k) * __ldg(c + k);

    // ---- main region: contiguous chunk range per block ----
    const int s0 = (int)(((long long)b       * CHM) / G);
    const int s1 = (int)(((long long)(b + 1) * CHM) / G);

    if (s0 < s1) {
        const int g0 = s0 << 10;
        // decode starting row (double seed + exact fixup)
        const double nd = 2.0 * (double)n - 1.0;
        int i = (int)((nd - sqrt(nd * nd - 8.0 * (double)g0)) * 0.5);
        if (i < 0) i = 0;
        if (i > n - 2) i = n - 2;
        int rb = (i * (2 * n - 1 - i)) >> 1;
        while (rb > g0) { --i; rb -= (n - 1 - i); }
        while (g0 >= rb + (n - 1 - i)) { rb += (n - 1 - i); ++i; }
        int re = rb + (n - 1 - i);

        const float4* cv = (const float4*)c2;
        const float4* xv = (const float4*)x;

        int ch = s0;
        while (ch < s1) {
            const int nb = (s1 - ch >= 2) ? 2 : 1;
            // coeff loads: induction-only addresses, batched in flight
            const float4 cfa = __ldcs(cv + (ch << 8) + t);
            float4 cfb;
            if (nb == 2) cfb = __ldcs(cv + ((ch + 1) << 8) + t);

            #pragma unroll
            for (int k = 0; k < 2; ++k) {
                if (k >= nb) break;
                const float4 cf = k ? cfb : cfa;
                const int cb = (ch + k) << 10;
                while (cb >= re) { rb = re; ++i; re += (n - 1 - i); }
                const int joffA = i + 1 - rb;

                if (cb + 1024 <= re) {
                    // uniform chunk: whole chunk inside row i
                    const int w0 = cb + joffA;
                    const int s  = w0 & 3;
                    const int fi = (w0 >> 2) + t;
                    const float4 f  = __ldg(xv + fi);
                    const float4 g4 = s ? __ldg(xv + fi + 1) : f;
                    const float4 xw = win(f, g4, s);
                    float p = cf.x * xw.x;
                    p = fmaf(cf.y, xw.y, p);
                    p = fmaf(cf.z, xw.z, p);
                    p = fmaf(cf.w, xw.w, p);
                    sum = fmaf(__ldg(x + i), p, sum);
                } else {
                    // boundary chunk: rows i (g < re) and i+1 (g >= re)
                    const int joffB = i + 2 - re;
                    const float xiA = __ldg(x + i);
                    const float xiB = __ldg(x + i + 1);
                    const int gb = cb + 4 * t;
                    {
                        const bool inA = (gb < re);
                        const float xv0 = __ldg(x + gb + (inA ? joffA : joffB));
                        sum = fmaf(cf.x * (inA ? xiA : xiB), xv0, sum);
                    }
                    {
                        const bool inA = (gb + 1 < re);
                        const float xv1 = __ldg(x + gb + 1 + (inA ? joffA : joffB));
                        sum = fmaf(cf.y * (inA ? xiA : xiB), xv1, sum);
                    }
                    {
                        const bool inA = (gb + 2 < re);
                        const float xv2 = __ldg(x + gb + 2 + (inA ? joffA : joffB));
                        sum = fmaf(cf.z * (inA ? xiA : xiB), xv2, sum);
                    }
                    {
                        const bool inA = (gb + 3 < re);
                        const float xv3 = __ldg(x + gb + 3 + (inA ? joffA : joffB));
                        sum = fmaf(cf.w * (inA ? xiA : xiB), xv3, sum);
                    }
                    rb = re; ++i; re += (n - 1 - i);
                }
            }
            ch += nb;
        }
    }

    // ---- corner region [CHM*1024, total): per-element decode ----
    {
        const double nd = 2.0 * (double)n - 1.0;
        for (int g = (CHM << 10) + b * TPB + t; g < total; g += G * TPB) {
            int i = (int)((nd - sqrt(nd * nd - 8.0 * (double)g)) * 0.5);
            if (i < 0) i = 0;
            if (i > n - 2) i = n - 2;
            int rb = (i * (2 * n - 1 - i)) >> 1;
            while (rb > g) { --i; rb -= (n - 1 - i); }
            while (g >= rb + (n - 1 - i)) { rb += (n - 1 - i); ++i; }
            const int j = g - rb + i + 1;
            sum = fmaf(__ldcs(c2 + g), __ldg(x + i) * __ldg(x + j), sum);
        }
    }

    // ---- block partial -> counter -> last block reduces + writes out ----
    __shared__ float wsum[TPB / 32];
    __shared__ int lastflag;
    float w = warp_sum(sum);
    if ((t & 31) == 0) wsum[t >> 5] = w;
    __syncthreads();
    if (t < 32) {
        float v = (t < TPB / 32) ? wsum[t] : 0.0f;
        v = warp_sum(v);
        if (t == 0) {
            g_parts[b] = v;
            __threadfence();
            unsigned int old = atomicInc(&g_ctr, (unsigned)(G - 1));
            lastflag = (old == (unsigned)(G - 1));
        }
    }
    __syncthreads();
    if (lastflag) {
        __threadfence();
        float v = 0.0f;
        for (int k = t; k < G; k += TPB) v += g_parts[k];
        float w2 = warp_sum(v);
        if ((t & 31) == 0) wsum[t >> 5] = w2;
        __syncthreads();
        if (t == 0) {
            float s2 = 0.0f;
            #pragma unroll
            for (int k = 0; k < TPB / 32; ++k) s2 += wsum[k];
            out[0] = s2;
        }
    }
}

extern "C" void kernel_launch(void* const* d_in, const int* in_sizes, int n_in,
                              void* d_out, int out_size) {
    const float* x = (const float*)d_in[0];
    const float* c = (const float*)d_in[1];
    float* out = (float*)d_out;
    const int n = in_sizes[0];   // 8192

    ham_kernel<<<NBLK, TPB>>>(x, c, out, n);
}